// round 5
// baseline (speedup 1.0000x reference)
#include <cuda_runtime.h>
#include <cstdint>

#define V_NUM 80000
#define P_NUM 20
#define C_OUT 64
#define NY 640
#define NX 640
#define B_NUM 4

static constexpr float BN_EPS = 0.001f;
static constexpr size_t PLANE  = (size_t)NY * NX;                 // 409600
static constexpr size_t CANVAS = (size_t)B_NUM * C_OUT * PLANE;   // 104857600
static constexpr int    MAP_N  = B_NUM * NY * NX;                 // 1638400

__device__ __constant__ float kVX   = 100.0f / 640.0f;
__device__ __constant__ float kXOFF = 100.0f / 640.0f * 0.5f - 50.0f;

// Scratch. g_map / g_pix are zero-initialized at module load; the
// self-validation scheme (g_pix[g_map[pix]] == pix) makes per-call clearing
// unnecessary.
__device__ float g_feats[(size_t)V_NUM * C_OUT];   // 20.5 MB
__device__ int   g_map[MAP_N];                     // pixel -> voxel id
__device__ int   g_pix[V_NUM];                     // voxel id -> pixel

// ---------------------------------------------------------------------------
// Kernel 1: per-voxel features -> g_feats (coalesced), id <-> pixel links.
// One warp per voxel; lane handles channels {lane, lane+32}.
// h = x*A + y*B + z*C + w*D + E_v   (BN folded; E_v per-voxel constant)
// Fold constants computed once per block by warp 0 into smem (no extra
// serialized launch). Inner point loop uses shfl-broadcast of the point each
// lane already loaded -> no memory ops in the loop.
// ---------------------------------------------------------------------------
__global__ void __launch_bounds__(128)
compute_feats_kernel(const float* __restrict__ voxels,
                     const int*   __restrict__ num_points,
                     const int*   __restrict__ coors,
                     const float* __restrict__ W,
                     const float* __restrict__ gamma,
                     const float* __restrict__ beta,
                     const float* __restrict__ rmean,
                     const float* __restrict__ rvar)
{
    // rows: 0:A 1:B 2:C 3:D 4:bb 5..9: sw4..sw8  (paired channels c, c+32)
    __shared__ float2 fold_s[10 * 32];

    const int lane = threadIdx.x & 31;

    if (threadIdx.x < 32) {
        const int t = threadIdx.x;
        const int c0 = t, c1 = t + 32;
        const float s0 = rsqrtf(rvar[c0] + BN_EPS) * gamma[c0];
        const float s1 = rsqrtf(rvar[c1] + BN_EPS) * gamma[c1];
        const float bb0 = beta[c0] - rmean[c0] * s0;
        const float bb1 = beta[c1] - rmean[c1] * s1;
        float sw0[9], sw1[9];
        #pragma unroll
        for (int i = 0; i < 9; i++) {
            sw0[i] = W[i * C_OUT + c0] * s0;
            sw1[i] = W[i * C_OUT + c1] * s1;
        }
        fold_s[0 * 32 + t] = make_float2(sw0[0] + sw0[4] + sw0[7],
                                         sw1[0] + sw1[4] + sw1[7]);   // A
        fold_s[1 * 32 + t] = make_float2(sw0[1] + sw0[5] + sw0[8],
                                         sw1[1] + sw1[5] + sw1[8]);   // B
        fold_s[2 * 32 + t] = make_float2(sw0[2] + sw0[6],
                                         sw1[2] + sw1[6]);            // C
        fold_s[3 * 32 + t] = make_float2(sw0[3], sw1[3]);             // D
        fold_s[4 * 32 + t] = make_float2(bb0, bb1);                   // bb
        #pragma unroll
        for (int i = 0; i < 5; i++)
            fold_s[(5 + i) * 32 + t] = make_float2(sw0[4 + i], sw1[4 + i]);
    }
    __syncthreads();

    const int v = blockIdx.x * (blockDim.x >> 5) + (threadIdx.x >> 5);
    if (v >= V_NUM) return;

    const float4* __restrict__ vox =
        reinterpret_cast<const float4*>(voxels) + (size_t)v * P_NUM;

    int npv = num_points[v];
    npv = npv < 0 ? 0 : (npv > P_NUM ? P_NUM : npv);

    // each lane loads its own point (also feeds the mean reduction)
    float4 myp = make_float4(0.f, 0.f, 0.f, 0.f);
    if (lane < npv) myp = vox[lane];

    float sx = myp.x, sy = myp.y, sz = myp.z;
    #pragma unroll
    for (int o = 16; o; o >>= 1) {
        sx += __shfl_xor_sync(0xffffffffu, sx, o);
        sy += __shfl_xor_sync(0xffffffffu, sy, o);
        sz += __shfl_xor_sync(0xffffffffu, sz, o);
    }
    const float inv_n = 1.0f / (float)(npv > 1 ? npv : 1);
    const float mx = sx * inv_n, my = sy * inv_n, mz = sz * inv_n;

    const int b  = coors[v * 4 + 0];
    const int yy = coors[v * 4 + 2];
    const int xx = coors[v * 4 + 3];
    const float cx = (float)xx * kVX + kXOFF;
    const float cy = (float)yy * kVX + kXOFF;

    const float2 A  = fold_s[0 * 32 + lane];
    const float2 B  = fold_s[1 * 32 + lane];
    const float2 C  = fold_s[2 * 32 + lane];
    const float2 D  = fold_s[3 * 32 + lane];
    const float2 bb = fold_s[4 * 32 + lane];
    const float2 s4 = fold_s[5 * 32 + lane];
    const float2 s5 = fold_s[6 * 32 + lane];
    const float2 s6 = fold_s[7 * 32 + lane];
    const float2 s7 = fold_s[8 * 32 + lane];
    const float2 s8 = fold_s[9 * 32 + lane];

    const float E0 = bb.x - (mx * s4.x + my * s5.x + mz * s6.x
                           + cx * s7.x + cy * s8.x);
    const float E1 = bb.y - (mx * s4.y + my * s5.y + mz * s6.y
                           + cx * s7.y + cy * s8.y);

    // masked (zero-feature) points contribute relu(BN bias) to the max
    float m0 = (npv < P_NUM) ? fmaxf(bb.x, 0.0f) : -3.4e38f;
    float m1 = (npv < P_NUM) ? fmaxf(bb.y, 0.0f) : -3.4e38f;

    for (int p = 0; p < npv; p++) {
        const float px = __shfl_sync(0xffffffffu, myp.x, p);
        const float py = __shfl_sync(0xffffffffu, myp.y, p);
        const float pz = __shfl_sync(0xffffffffu, myp.z, p);
        const float pw = __shfl_sync(0xffffffffu, myp.w, p);
        float h0 = fmaf(px, A.x, E0);
        float h1 = fmaf(px, A.y, E1);
        h0 = fmaf(py, B.x, h0);   h1 = fmaf(py, B.y, h1);
        h0 = fmaf(pz, C.x, h0);   h1 = fmaf(pz, C.y, h1);
        h0 = fmaf(pw, D.x, h0);   h1 = fmaf(pw, D.y, h1);
        m0 = fmaxf(m0, fmaxf(h0, 0.0f));
        m1 = fmaxf(m1, fmaxf(h1, 0.0f));
    }

    g_feats[(size_t)v * C_OUT + lane]      = m0;
    g_feats[(size_t)v * C_OUT + lane + 32] = m1;
    if (lane == 0) {
        const int pix = b * (NY * NX) + yy * NX + xx;
        g_map[pix] = v;
        g_pix[v]   = pix;
    }
}

// ---------------------------------------------------------------------------
// Kernel 2: coalesced render of canvas + occ.
// Block = 256 threads, owns 128 pixels of one (b,y) row, all 64 channels.
// ---------------------------------------------------------------------------
__global__ void __launch_bounds__(256)
render_kernel(float* __restrict__ out)
{
    __shared__ int map_s[128];

    const int b  = blockIdx.z;
    const int y  = blockIdx.y;
    const int x0 = blockIdx.x * 128;
    const int t  = threadIdx.x;

    const int pix_base = b * (NY * NX) + y * NX + x0;
    if (t < 128) {
        const int pix = pix_base + t;
        int v = g_map[pix];
        if (g_pix[v] != pix) v = -1;   // stale / zero-init -> invalid
        map_s[t] = v;
    }
    __syncthreads();

    const int xq  = (t & 31) * 4;
    const int row = t >> 5;            // 0..7

    const int v0 = map_s[xq + 0];
    const int v1 = map_s[xq + 1];
    const int v2 = map_s[xq + 2];
    const int v3 = map_s[xq + 3];

    const size_t out_xbase = (size_t)y * NX + x0 + xq;

    #pragma unroll
    for (int k = 0; k < 8; k++) {
        const int c = row + k * 8;
        float4 val = make_float4(0.f, 0.f, 0.f, 0.f);
        if (v0 >= 0) val.x = g_feats[(size_t)v0 * C_OUT + c];
        if (v1 >= 0) val.y = g_feats[(size_t)v1 * C_OUT + c];
        if (v2 >= 0) val.z = g_feats[(size_t)v2 * C_OUT + c];
        if (v3 >= 0) val.w = g_feats[(size_t)v3 * C_OUT + c];
        float4* dst = reinterpret_cast<float4*>(
            out + ((size_t)(b * C_OUT + c)) * PLANE + out_xbase);
        __stcs(dst, val);              // streaming: keep feats/map in L2
    }

    if (t < 32) {
        float4 occ = make_float4(v0 >= 0 ? 1.f : 0.f,
                                 v1 >= 0 ? 1.f : 0.f,
                                 v2 >= 0 ? 1.f : 0.f,
                                 v3 >= 0 ? 1.f : 0.f);
        float4* dst = reinterpret_cast<float4*>(
            out + CANVAS + (size_t)b * PLANE + out_xbase);
        __stcs(dst, occ);
    }
}

extern "C" void kernel_launch(void* const* d_in, const int* in_sizes, int n_in,
                              void* d_out, int out_size)
{
    const float* voxels     = (const float*)d_in[0];
    const int*   num_points = (const int*)  d_in[1];
    const int*   coors      = (const int*)  d_in[2];
    const float* W          = (const float*)d_in[3];
    const float* gamma      = (const float*)d_in[4];
    const float* beta       = (const float*)d_in[5];
    const float* rmean      = (const float*)d_in[6];
    const float* rvar       = (const float*)d_in[7];
    float* out = (float*)d_out;

    compute_feats_kernel<<<(V_NUM + 3) / 4, 128>>>(voxels, num_points, coors,
                                                   W, gamma, beta, rmean, rvar);

    dim3 grid(NX / 128, NY, B_NUM);
    render_kernel<<<grid, 256>>>(out);
}